// round 3
// baseline (speedup 1.0000x reference)
#include <cuda_runtime.h>

#define N_NODES  32768
#define N_EDGES  16384
#define D_PER_N  4
#define K_PER_E  8
#define ODIM     128

// ---------------- scratch (static device allocations) ----------------
__device__ float g_A[384 * 128];                    // folded weights: [Aq;Ak;Av]
__device__ float g_Bk[128 * 64];                    // Wk @ W_edge
__device__ float g_bias[384];                       // [bq ; 0 ; bv]
__device__ float g_QKV[(size_t)N_NODES * 384];      // per node: Q | KN | VN
__device__ float g_KE[(size_t)N_EDGES * 128];       // edge key part (+bk)
__device__ float g_CTX[(size_t)N_NODES * 128];      // attention output

// ---------------- prep: fold weights ----------------
// g_A[r][j]  = W_{q/k/v}[r%128][:] . W_lin[:][j]   (r<384)
// g_Bk[r][j] = Wk[r][:] . W_edge[:][j]
__global__ void prep_kernel(const float* __restrict__ W_lin,
                            const float* __restrict__ W_edge,
                            const float* __restrict__ Wq,
                            const float* __restrict__ Wk,
                            const float* __restrict__ Wv,
                            const float* __restrict__ bq,
                            const float* __restrict__ bv)
{
    int b = blockIdx.x;
    int j = threadIdx.x;
    if (b < 384) {
        const float* Ws = (b < 128) ? Wq : (b < 256 ? Wk : Wv);
        int r = b & 127;
        float acc = 0.f;
        #pragma unroll 8
        for (int k = 0; k < 128; k++)
            acc = fmaf(Ws[r * 128 + k], W_lin[k * 128 + j], acc);
        g_A[b * 128 + j] = acc;
    } else if (b < 512) {
        int r = b - 384;
        if (j < 64) {
            float acc = 0.f;
            #pragma unroll 8
            for (int o = 0; o < 128; o++)
                acc = fmaf(Wk[r * 128 + o], W_edge[o * 64 + j], acc);
            g_Bk[r * 64 + j] = acc;
        }
    } else {
        g_bias[j]       = bq[j];
        g_bias[128 + j] = 0.f;
        g_bias[256 + j] = bv[j];
    }
}

// ---------------- tiled SGEMM:  C[m][n] = X[m][:KDIM] . A[n][:KDIM] + bias[n] ----------------
// BM=BN=128, BK=8, 256 threads, 8x8 per thread.
template<int KDIM, bool RELU>
__global__ __launch_bounds__(256)
void gemm_nt(const float* __restrict__ X,
             const float* __restrict__ A,
             const float* __restrict__ bias,
             float* __restrict__ C, int ldc)
{
    __shared__ float Xs[8][128];
    __shared__ float As[8][128];

    const int t   = threadIdx.x;
    const int tx  = t & 15;          // col fragment
    const int ty  = t >> 4;          // row fragment
    const int mB  = blockIdx.x * 128;
    const int nB  = blockIdx.y * 128;
    const int lrow = t >> 1;         // 0..127
    const int lseg = (t & 1) * 4;    // 0 or 4

    float acc[8][8];
    #pragma unroll
    for (int i = 0; i < 8; i++)
        #pragma unroll
        for (int j = 0; j < 8; j++) acc[i][j] = 0.f;

    const float* Xp = X + (size_t)(mB + lrow) * KDIM + lseg;
    const float* Ap = A + (size_t)(nB + lrow) * KDIM + lseg;

    for (int k0 = 0; k0 < KDIM; k0 += 8) {
        float4 xv = *(const float4*)(Xp + k0);
        float4 av = *(const float4*)(Ap + k0);
        __syncthreads();
        Xs[lseg + 0][lrow] = xv.x; Xs[lseg + 1][lrow] = xv.y;
        Xs[lseg + 2][lrow] = xv.z; Xs[lseg + 3][lrow] = xv.w;
        As[lseg + 0][lrow] = av.x; As[lseg + 1][lrow] = av.y;
        As[lseg + 2][lrow] = av.z; As[lseg + 3][lrow] = av.w;
        __syncthreads();
        #pragma unroll
        for (int kk = 0; kk < 8; kk++) {
            float xf[8], af[8];
            #pragma unroll
            for (int i = 0; i < 8; i++) xf[i] = Xs[kk][ty * 8 + i];
            #pragma unroll
            for (int j = 0; j < 8; j++) af[j] = As[kk][tx * 8 + j];
            #pragma unroll
            for (int i = 0; i < 8; i++)
                #pragma unroll
                for (int j = 0; j < 8; j++)
                    acc[i][j] = fmaf(xf[i], af[j], acc[i][j]);
        }
    }

    #pragma unroll
    for (int i = 0; i < 8; i++) {
        int m = mB + ty * 8 + i;
        float* cp = C + (size_t)m * ldc + nB + tx * 8;
        float o[8];
        #pragma unroll
        for (int j = 0; j < 8; j++) {
            float v = acc[i][j] + bias[nB + tx * 8 + j];
            if (RELU) v = fmaxf(v, 0.f);
            o[j] = v;
        }
        *(float4*)(cp)     = make_float4(o[0], o[1], o[2], o[3]);
        *(float4*)(cp + 4) = make_float4(o[4], o[5], o[6], o[7]);
    }
}

// ---------------- attention: one block (128 thr) per node ----------------
__global__ __launch_bounds__(128)
void attn_kernel(const int* __restrict__ node_edges,
                 const int* __restrict__ edge_nodes)
{
    __shared__ float ks[32][129];   // stride 129: conflict-free for stride-l reads
    __shared__ float vs[32][129];
    __shared__ float qs[128];
    __shared__ float sc[8][33];
    __shared__ int   s_e[4];
    __shared__ int   s_u[32];

    const int n = blockIdx.x;
    const int t = threadIdx.x;

    if (t < 4) s_e[t] = node_edges[n * 4 + t];
    qs[t] = g_QKV[(size_t)n * 384 + t];
    __syncthreads();
    if (t < 32) s_u[t] = edge_nodes[s_e[t >> 3] * 8 + (t & 7)];
    __syncthreads();

    // gather keys/values: key = KN[u] + KE[e], val = VN[u]  (coalesced 512B rows)
    #pragma unroll 4
    for (int l = 0; l < 32; l++) {
        int u = s_u[l];
        int e = s_e[l >> 3];
        ks[l][t] = g_QKV[(size_t)u * 384 + 128 + t] + g_KE[(size_t)e * 128 + t];
        vs[l][t] = g_QKV[(size_t)u * 384 + 256 + t];
    }
    __syncthreads();

    // scores: 256 (h,l) pairs over 128 threads, 2 each
    #pragma unroll
    for (int i = 0; i < 2; i++) {
        int h = (t >> 5) + (i << 2);
        int l = t & 31;
        float s = 0.f;
        #pragma unroll
        for (int d = 0; d < 16; d++)
            s = fmaf(qs[h * 16 + d], ks[l][h * 16 + d], s);
        sc[h][l] = s * 0.25f;        // 1/sqrt(hd=16)
    }
    __syncthreads();

    // softmax over l=0..31: warp w handles heads w and w+4
    {
        int lane = t & 31;
        int w = t >> 5;
        #pragma unroll
        for (int i = 0; i < 2; i++) {
            int h = w + (i << 2);
            float s = sc[h][lane];
            float m = s;
            #pragma unroll
            for (int o = 16; o > 0; o >>= 1)
                m = fmaxf(m, __shfl_xor_sync(0xffffffffu, m, o));
            float e = __expf(s - m);
            float sum = e;
            #pragma unroll
            for (int o = 16; o > 0; o >>= 1)
                sum += __shfl_xor_sync(0xffffffffu, sum, o);
            sc[h][lane] = e / sum;
        }
    }
    __syncthreads();

    // ctx[t] = sum_l attn[h(t)][l] * V[l][t]
    {
        float c = 0.f;
        int h = t >> 4;
        #pragma unroll
        for (int l = 0; l < 32; l++)
            c = fmaf(sc[h][l], vs[l][t], c);
        g_CTX[(size_t)n * 128 + t] = c;
    }
}

// ---------------- launch ----------------
extern "C" void kernel_launch(void* const* d_in, const int* in_sizes, int n_in,
                              void* d_out, int out_size)
{
    const float* x          = (const float*)d_in[0];
    const float* edge_attr  = (const float*)d_in[1];
    const int*   node_edges = (const int*)  d_in[2];
    const int*   edge_nodes = (const int*)  d_in[3];
    const float* W_lin      = (const float*)d_in[4];
    const float* W_edge     = (const float*)d_in[5];
    const float* Wq         = (const float*)d_in[6];
    const float* Wk         = (const float*)d_in[7];
    const float* Wv         = (const float*)d_in[8];
    const float* bq         = (const float*)d_in[9];
    const float* bk         = (const float*)d_in[10];
    const float* bv         = (const float*)d_in[11];
    const float* Wo         = (const float*)d_in[12];
    const float* bo         = (const float*)d_in[13];
    float*       out        = (float*)d_out;

    void *pA, *pBk, *pbias, *pQKV, *pKE, *pCTX;
    cudaGetSymbolAddress(&pA,   g_A);
    cudaGetSymbolAddress(&pBk,  g_Bk);
    cudaGetSymbolAddress(&pbias,g_bias);
    cudaGetSymbolAddress(&pQKV, g_QKV);
    cudaGetSymbolAddress(&pKE,  g_KE);
    cudaGetSymbolAddress(&pCTX, g_CTX);

    // 1) fold weights
    prep_kernel<<<513, 128>>>(W_lin, W_edge, Wq, Wk, Wv, bq, bv);

    // 2) QKV = x @ [Aq;Ak;Av]^T + [bq;0;bv]   -> [N, 384]
    gemm_nt<128, false><<<dim3(N_NODES / 128, 3), 256>>>(
        x, (const float*)pA, (const float*)pbias, (float*)pQKV, 384);

    // 3) KE = edge_attr @ (Wk W_edge)^T + bk  -> [E, 128]
    gemm_nt<64, false><<<dim3(N_EDGES / 128, 1), 256>>>(
        edge_attr, (const float*)pBk, bk, (float*)pKE, 128);

    // 4) gather + attention -> ctx [N, 128]
    attn_kernel<<<N_NODES, 128>>>(node_edges, edge_nodes);

    // 5) out = relu(ctx @ Wo^T + bo)
    gemm_nt<128, true><<<dim3(N_NODES / 128, 1), 256>>>(
        (const float*)pCTX, Wo, bo, out, 128);
}

// round 4
// speedup vs baseline: 1.9089x; 1.9089x over previous
#include <cuda_runtime.h>

#define N_NODES  32768
#define N_EDGES  16384
#define D_PER_N  4
#define K_PER_E  8
#define ODIM     128

// ---------------- scratch (static device allocations) ----------------
__device__ float g_A[384 * 128];                    // folded weights: [Aq;Ak;Av]
__device__ float g_Bk[128 * 64];                    // Wk @ W_edge
__device__ float g_bias[384];                       // [bq ; 0 ; bv]
__device__ float g_QKV[(size_t)N_NODES * 384];      // per node: Q | KN | VN
__device__ float g_KE[(size_t)N_EDGES * 128];       // edge key part (+bk)
__device__ float g_CTX[(size_t)N_NODES * 128];      // attention output

// ---------------- prep: fold weights ----------------
__global__ void prep_kernel(const float* __restrict__ W_lin,
                            const float* __restrict__ W_edge,
                            const float* __restrict__ Wq,
                            const float* __restrict__ Wk,
                            const float* __restrict__ Wv,
                            const float* __restrict__ bq,
                            const float* __restrict__ bv)
{
    int b = blockIdx.x;
    int j = threadIdx.x;
    if (b < 384) {
        const float* Ws = (b < 128) ? Wq : (b < 256 ? Wk : Wv);
        int r = b & 127;
        float acc = 0.f;
        #pragma unroll 8
        for (int k = 0; k < 128; k++)
            acc = fmaf(Ws[r * 128 + k], W_lin[k * 128 + j], acc);
        g_A[b * 128 + j] = acc;
    } else if (b < 512) {
        int r = b - 384;
        if (j < 64) {
            float acc = 0.f;
            #pragma unroll 8
            for (int o = 0; o < 128; o++)
                acc = fmaf(Wk[r * 128 + o], W_edge[o * 64 + j], acc);
            g_Bk[r * 64 + j] = acc;
        }
    } else {
        g_bias[j]       = bq[j];
        g_bias[128 + j] = 0.f;
        g_bias[256 + j] = bv[j];
    }
}

// ---------------- tiled SGEMM:  C[m][n] = X[m][:KDIM] . A[n][:KDIM] + bias[n] ----------------
template<int KDIM, bool RELU>
__global__ __launch_bounds__(256)
void gemm_nt(const float* __restrict__ X,
             const float* __restrict__ A,
             const float* __restrict__ bias,
             float* __restrict__ C, int ldc)
{
    __shared__ float Xs[8][128];
    __shared__ float As[8][128];

    const int t   = threadIdx.x;
    const int tx  = t & 15;
    const int ty  = t >> 4;
    const int mB  = blockIdx.x * 128;
    const int nB  = blockIdx.y * 128;
    const int lrow = t >> 1;
    const int lseg = (t & 1) * 4;

    float acc[8][8];
    #pragma unroll
    for (int i = 0; i < 8; i++)
        #pragma unroll
        for (int j = 0; j < 8; j++) acc[i][j] = 0.f;

    const float* Xp = X + (size_t)(mB + lrow) * KDIM + lseg;
    const float* Ap = A + (size_t)(nB + lrow) * KDIM + lseg;

    for (int k0 = 0; k0 < KDIM; k0 += 8) {
        float4 xv = *(const float4*)(Xp + k0);
        float4 av = *(const float4*)(Ap + k0);
        __syncthreads();
        Xs[lseg + 0][lrow] = xv.x; Xs[lseg + 1][lrow] = xv.y;
        Xs[lseg + 2][lrow] = xv.z; Xs[lseg + 3][lrow] = xv.w;
        As[lseg + 0][lrow] = av.x; As[lseg + 1][lrow] = av.y;
        As[lseg + 2][lrow] = av.z; As[lseg + 3][lrow] = av.w;
        __syncthreads();
        #pragma unroll
        for (int kk = 0; kk < 8; kk++) {
            float xf[8], af[8];
            #pragma unroll
            for (int i = 0; i < 8; i++) xf[i] = Xs[kk][ty * 8 + i];
            #pragma unroll
            for (int j = 0; j < 8; j++) af[j] = As[kk][tx * 8 + j];
            #pragma unroll
            for (int i = 0; i < 8; i++)
                #pragma unroll
                for (int j = 0; j < 8; j++)
                    acc[i][j] = fmaf(xf[i], af[j], acc[i][j]);
        }
    }

    #pragma unroll
    for (int i = 0; i < 8; i++) {
        int m = mB + ty * 8 + i;
        float* cp = C + (size_t)m * ldc + nB + tx * 8;
        float o[8];
        #pragma unroll
        for (int j = 0; j < 8; j++) {
            float v = acc[i][j] + bias[nB + tx * 8 + j];
            if (RELU) v = fmaxf(v, 0.f);
            o[j] = v;
        }
        *(float4*)(cp)     = make_float4(o[0], o[1], o[2], o[3]);
        *(float4*)(cp + 4) = make_float4(o[4], o[5], o[6], o[7]);
    }
}

// ---------------- attention: one block (128 thr) per node, register-resident ----------------
// warp w owns rows l in [8w, 8w+8)  (all share edge slot e = s_e[w], since l>>3 == w)
// lane la covers dims [4*la, 4*la+4) as a float4; those 4 dims lie in head h = la>>2.
__global__ __launch_bounds__(128)
void attn_kernel(const int* __restrict__ node_edges,
                 const int* __restrict__ edge_nodes)
{
    __shared__ float sc[8][33];      // [head][l] scores then attn weights
    __shared__ float part[4][128];   // cross-warp ctx reduction
    __shared__ int   s_e[4];
    __shared__ int   s_u[32];

    const int n  = blockIdx.x;
    const int t  = threadIdx.x;
    const int w  = t >> 5;
    const int la = t & 31;
    const int hg = la >> 2;          // head this lane's dims belong to

    if (t < 4) s_e[t] = node_edges[n * 4 + t];
    __syncthreads();
    if (t < 32) s_u[t] = edge_nodes[s_e[t >> 3] * 8 + (t & 7)];

    // q fragment: dims 4*la .. 4*la+3 (same for every warp)
    const float4 q4 = *(const float4*)(g_QKV + n * 384 + la * 4);
    __syncthreads();

    // ---- edge-key dot (once per warp; stays in register) ----
    float p_e;
    {
        int e = s_e[w];
        float4 k4 = *(const float4*)(g_KE + e * 128 + la * 4);
        float p = q4.x * k4.x;
        p = fmaf(q4.y, k4.y, p);
        p = fmaf(q4.z, k4.z, p);
        p = fmaf(q4.w, k4.w, p);
        p += __shfl_xor_sync(0xffffffffu, p, 1);
        p += __shfl_xor_sync(0xffffffffu, p, 2);
        p_e = p;                     // all 4 lanes of each head group hold the head's edge dot
    }

    // ---- node-key dots: 8 rows per warp, fully unrolled for MLP ----
    #pragma unroll
    for (int i = 0; i < 8; i++) {
        int l = w * 8 + i;
        int u = s_u[l];
        float4 k4 = *(const float4*)(g_QKV + u * 384 + 128 + la * 4);
        float p = q4.x * k4.x;
        p = fmaf(q4.y, k4.y, p);
        p = fmaf(q4.z, k4.z, p);
        p = fmaf(q4.w, k4.w, p);
        p += __shfl_xor_sync(0xffffffffu, p, 1);
        p += __shfl_xor_sync(0xffffffffu, p, 2);
        if ((la & 3) == 0)
            sc[hg][l] = (p + p_e) * 0.25f;   // 1/sqrt(hd=16)
    }
    __syncthreads();

    // ---- softmax over l=0..31: warp w handles heads w and w+4 ----
    #pragma unroll
    for (int i = 0; i < 2; i++) {
        int hh = w + (i << 2);
        float s = sc[hh][la];
        float m = s;
        #pragma unroll
        for (int o = 16; o > 0; o >>= 1)
            m = fmaxf(m, __shfl_xor_sync(0xffffffffu, m, o));
        float e = __expf(s - m);
        float sum = e;
        #pragma unroll
        for (int o = 16; o > 0; o >>= 1)
            sum += __shfl_xor_sync(0xffffffffu, sum, o);
        sc[hh][la] = e / sum;
    }
    __syncthreads();

    // ---- ctx: warp w accumulates its 8 rows of V, then cross-warp reduce ----
    float4 acc = make_float4(0.f, 0.f, 0.f, 0.f);
    #pragma unroll
    for (int i = 0; i < 8; i++) {
        int l = w * 8 + i;
        int u = s_u[l];
        float4 v4 = *(const float4*)(g_QKV + u * 384 + 256 + la * 4);
        float a = sc[hg][l];
        acc.x = fmaf(a, v4.x, acc.x);
        acc.y = fmaf(a, v4.y, acc.y);
        acc.z = fmaf(a, v4.z, acc.z);
        acc.w = fmaf(a, v4.w, acc.w);
    }
    *(float4*)(&part[w][la * 4]) = acc;
    __syncthreads();

    g_CTX[n * 128 + t] = part[0][t] + part[1][t] + part[2][t] + part[3][t];
}

// ---------------- launch ----------------
extern "C" void kernel_launch(void* const* d_in, const int* in_sizes, int n_in,
                              void* d_out, int out_size)
{
    const float* x          = (const float*)d_in[0];
    const float* edge_attr  = (const float*)d_in[1];
    const int*   node_edges = (const int*)  d_in[2];
    const int*   edge_nodes = (const int*)  d_in[3];
    const float* W_lin      = (const float*)d_in[4];
    const float* W_edge     = (const float*)d_in[5];
    const float* Wq         = (const float*)d_in[6];
    const float* Wk         = (const float*)d_in[7];
    const float* Wv         = (const float*)d_in[8];
    const float* bq         = (const float*)d_in[9];
    const float* bk         = (const float*)d_in[10];
    const float* bv         = (const float*)d_in[11];
    const float* Wo         = (const float*)d_in[12];
    const float* bo         = (const float*)d_in[13];
    float*       out        = (float*)d_out;

    void *pA, *pBk, *pbias, *pQKV, *pKE, *pCTX;
    cudaGetSymbolAddress(&pA,   g_A);
    cudaGetSymbolAddress(&pBk,  g_Bk);
    cudaGetSymbolAddress(&pbias,g_bias);
    cudaGetSymbolAddress(&pQKV, g_QKV);
    cudaGetSymbolAddress(&pKE,  g_KE);
    cudaGetSymbolAddress(&pCTX, g_CTX);

    // 1) fold weights
    prep_kernel<<<513, 128>>>(W_lin, W_edge, Wq, Wk, Wv, bq, bv);

    // 2) QKV = x @ [Aq;Ak;Av]^T + [bq;0;bv]   -> [N, 384]
    gemm_nt<128, false><<<dim3(N_NODES / 128, 3), 256>>>(
        x, (const float*)pA, (const float*)pbias, (float*)pQKV, 384);

    // 3) KE = edge_attr @ (Wk W_edge)^T + bk  -> [E, 128]
    gemm_nt<64, false><<<dim3(N_EDGES / 128, 1), 256>>>(
        edge_attr, (const float*)pBk, bk, (float*)pKE, 128);

    // 4) gather + attention -> ctx [N, 128]
    attn_kernel<<<N_NODES, 128>>>(node_edges, edge_nodes);

    // 5) out = relu(ctx @ Wo^T + bo)
    gemm_nt<128, true><<<dim3(N_NODES / 128, 1), 256>>>(
        (const float*)pCTX, Wo, bo, out, 128);
}